// round 1
// baseline (speedup 1.0000x reference)
#include <cuda_runtime.h>
#include <math.h>

#define CD   1024
#define CH   16
#define CFF  4096
#define CB   8
#define CN   1024
#define NTOK (CB*CN)   // 8192

// ---------------- scratch (no allocations allowed) ----------------
__device__ float g_xn [NTOK*CD];      // 32 MB : layernorm1(x)
__device__ float g_qkv[NTOK*3*CD];    // 96 MB : qkv projection
__device__ float g_ao [NTOK*CD];      // 32 MB : attention output (b,n,h*dh)
__device__ float g_x1 [NTOK*CD];      // 32 MB : attn + residual
__device__ float g_x2 [NTOK*CD];      // 32 MB : layernorm2(x1)
__device__ float g_h  [NTOK*CFF];     // 128 MB: gelu(lin1)

// ---------------- LayerNorm: one block per row of 1024 ----------------
__global__ void __launch_bounds__(256) layernorm_k(
    const float* __restrict__ x, const float* __restrict__ w,
    const float* __restrict__ b, float* __restrict__ y)
{
    int row = blockIdx.x;
    int tid = threadIdx.x;
    const float4* xr = (const float4*)(x + (size_t)row * CD);
    float4 xv = xr[tid];
    float s  = xv.x + xv.y + xv.z + xv.w;
    float ss = xv.x*xv.x + xv.y*xv.y + xv.z*xv.z + xv.w*xv.w;
    #pragma unroll
    for (int o = 16; o; o >>= 1) {
        s  += __shfl_xor_sync(0xffffffffu, s,  o);
        ss += __shfl_xor_sync(0xffffffffu, ss, o);
    }
    __shared__ float sm1[8], sm2[8];
    if ((tid & 31) == 0) { sm1[tid >> 5] = s; sm2[tid >> 5] = ss; }
    __syncthreads();
    float ts = 0.f, tss = 0.f;
    #pragma unroll
    for (int i = 0; i < 8; i++) { ts += sm1[i]; tss += sm2[i]; }
    float mu   = ts * (1.0f / CD);
    float var  = tss * (1.0f / CD) - mu * mu;
    float rstd = rsqrtf(var + 1e-5f);
    float4 wv = ((const float4*)w)[tid];
    float4 bv = ((const float4*)b)[tid];
    float4 ov;
    ov.x = (xv.x - mu) * rstd * wv.x + bv.x;
    ov.y = (xv.y - mu) * rstd * wv.y + bv.y;
    ov.z = (xv.z - mu) * rstd * wv.z + bv.z;
    ov.w = (xv.w - mu) * rstd * wv.w + bv.w;
    ((float4*)(y + (size_t)row * CD))[tid] = ov;
}

// ---------------- NT GEMM: C[M,N] = A[M,K] * B[N,K]^T (+ epilogue) -----
// EPI 0: none   EPI 1: +bias[n] + res[m,n]   EPI 2: gelu(+bias[n])
template<int EPI>
__global__ void __launch_bounds__(256) gemm_nt(
    const float* __restrict__ A, const float* __restrict__ B,
    const float* __restrict__ bias, const float* __restrict__ res,
    float* __restrict__ C, int M, int N, int K)
{
    __shared__ float As[16][128];
    __shared__ float Bs[16][128];
    int tid = threadIdx.x;
    int tx = tid & 15, ty = tid >> 4;
    const float* Ab = A + (size_t)blockIdx.y * 128 * K;
    const float* Bb = B + (size_t)blockIdx.x * 128 * K;
    float acc[8][8] = {};
    int lr = tid >> 2;           // 0..63
    int lc = (tid & 3) << 2;     // 0,4,8,12

    for (int k0 = 0; k0 < K; k0 += 16) {
        #pragma unroll
        for (int rr = 0; rr < 2; rr++) {
            int row = lr + rr * 64;
            float4 av = *(const float4*)(Ab + (size_t)row * K + k0 + lc);
            As[lc+0][row] = av.x; As[lc+1][row] = av.y;
            As[lc+2][row] = av.z; As[lc+3][row] = av.w;
            float4 bv = *(const float4*)(Bb + (size_t)row * K + k0 + lc);
            Bs[lc+0][row] = bv.x; Bs[lc+1][row] = bv.y;
            Bs[lc+2][row] = bv.z; Bs[lc+3][row] = bv.w;
        }
        __syncthreads();
        #pragma unroll
        for (int k = 0; k < 16; k++) {
            float4 a0 = *(const float4*)&As[k][ty*8];
            float4 a1 = *(const float4*)&As[k][ty*8+4];
            float4 b0 = *(const float4*)&Bs[k][tx*8];
            float4 b1 = *(const float4*)&Bs[k][tx*8+4];
            float a[8] = {a0.x,a0.y,a0.z,a0.w,a1.x,a1.y,a1.z,a1.w};
            float b[8] = {b0.x,b0.y,b0.z,b0.w,b1.x,b1.y,b1.z,b1.w};
            #pragma unroll
            for (int i = 0; i < 8; i++)
                #pragma unroll
                for (int j = 0; j < 8; j++)
                    acc[i][j] += a[i] * b[j];
        }
        __syncthreads();
    }

    int m0 = blockIdx.y * 128 + ty * 8;
    int n0 = blockIdx.x * 128 + tx * 8;
    #pragma unroll
    for (int i = 0; i < 8; i++) {
        size_t base = (size_t)(m0 + i) * N + n0;
        float v[8];
        #pragma unroll
        for (int j = 0; j < 8; j++) {
            float t = acc[i][j];
            if (EPI >= 1) t += bias[n0 + j];
            if (EPI == 1) t += res[base + j];
            if (EPI == 2) t = t * normcdff(t);   // exact gelu
            v[j] = t;
        }
        *(float4*)(C + base)     = make_float4(v[0], v[1], v[2], v[3]);
        *(float4*)(C + base + 4) = make_float4(v[4], v[5], v[6], v[7]);
    }
}

// ---------------- Flash attention: one block per (b, h, 64-row q tile) ----
// qkv layout: [(b*N+n), 3*D] with column = which*D + h*64 + d
// out layout: [(b*N+n), D]   with column = h*64 + d
__global__ void __launch_bounds__(256) flash_k(
    const float* __restrict__ qkv, const int* __restrict__ ids,
    float* __restrict__ o)
{
    extern __shared__ float sm[];
    float* Qs    = sm;                 // [64][64], Qs[d*64+q], pre-scaled
    float* KP    = sm + 4096;          // [64][65], Ks_t[d*65+k] then Ps[k*65+q]
    float* Vs    = sm + 4096 + 4160;   // [64][64], Vs[k*64+d]
    float* mrow  = Vs + 4096;          // 64
    float* lrow  = mrow + 64;          // 64
    float* maskb = lrow + 64;          // 64

    const int tid = threadIdx.x;
    const int tx = tid & 15, ty = tid >> 4;
    const int qt = blockIdx.x, h = blockIdx.y, b = blockIdx.z;
    const int q0 = qt * 64;
    const size_t rstr = 3 * CD;
    const float scale = 0.125f;        // dh^-0.5, dh=64

    // load Q tile transposed (Qs[d][q]), pre-scaled
    for (int s5 = tid; s5 < 1024; s5 += 256) {
        int r = s5 >> 4, c4 = (s5 & 15) << 2;
        const float* gp = qkv + ((size_t)(b*CN + q0 + r)) * rstr + h*64 + c4;
        float4 v = *(const float4*)gp;
        Qs[(c4+0)*64 + r] = v.x * scale;
        Qs[(c4+1)*64 + r] = v.y * scale;
        Qs[(c4+2)*64 + r] = v.z * scale;
        Qs[(c4+3)*64 + r] = v.w * scale;
    }
    if (tid < 64) { mrow[tid] = -1e30f; lrow[tid] = 0.f; }

    float acc[4][4] = {};

    for (int kt = 0; kt < 16; kt++) {
        int k0 = kt * 64;
        __syncthreads();  // previous-iter consumers done (also covers Q load on kt=0)
        for (int s5 = tid; s5 < 1024; s5 += 256) {
            int r = s5 >> 4, c4 = (s5 & 15) << 2;
            const float* gk = qkv + ((size_t)(b*CN + k0 + r)) * rstr + CD   + h*64 + c4;
            float4 v = *(const float4*)gk;
            KP[(c4+0)*65 + r] = v.x; KP[(c4+1)*65 + r] = v.y;
            KP[(c4+2)*65 + r] = v.z; KP[(c4+3)*65 + r] = v.w;
            const float* gv = qkv + ((size_t)(b*CN + k0 + r)) * rstr + 2*CD + h*64 + c4;
            *(float4*)&Vs[r*64 + c4] = *(const float4*)gv;
        }
        if (tid < 64) maskb[tid] = -1.25e8f * (float)ids[b*CN + k0 + tid]; // (-1e9)*scale
        __syncthreads();

        // S tile (64x64): s[i][j] for q = ty*4+i, k = tx*4+j
        float s4[4][4] = {};
        #pragma unroll 8
        for (int d = 0; d < 64; d++) {
            float4 a = *(const float4*)&Qs[d*64 + ty*4];
            float b0 = KP[d*65 + tx*4 + 0];
            float b1 = KP[d*65 + tx*4 + 1];
            float b2 = KP[d*65 + tx*4 + 2];
            float b3 = KP[d*65 + tx*4 + 3];
            s4[0][0] += a.x*b0; s4[0][1] += a.x*b1; s4[0][2] += a.x*b2; s4[0][3] += a.x*b3;
            s4[1][0] += a.y*b0; s4[1][1] += a.y*b1; s4[1][2] += a.y*b2; s4[1][3] += a.y*b3;
            s4[2][0] += a.z*b0; s4[2][1] += a.z*b1; s4[2][2] += a.z*b2; s4[2][3] += a.z*b3;
            s4[3][0] += a.w*b0; s4[3][1] += a.w*b1; s4[3][2] += a.w*b2; s4[3][3] += a.w*b3;
        }
        float mb0 = maskb[tx*4+0], mb1 = maskb[tx*4+1], mb2 = maskb[tx*4+2], mb3 = maskb[tx*4+3];
        #pragma unroll
        for (int i = 0; i < 4; i++) {
            s4[i][0] += mb0; s4[i][1] += mb1; s4[i][2] += mb2; s4[i][3] += mb3;
        }

        // online softmax, one row group per 16-lane half-warp
        #pragma unroll
        for (int i = 0; i < 4; i++) {
            float tmax = fmaxf(fmaxf(s4[i][0], s4[i][1]), fmaxf(s4[i][2], s4[i][3]));
            #pragma unroll
            for (int off = 8; off; off >>= 1)
                tmax = fmaxf(tmax, __shfl_xor_sync(0xffffffffu, tmax, off));
            int row = ty*4 + i;
            float mold = mrow[row];
            float mnew = fmaxf(mold, tmax);
            float al   = __expf(mold - mnew);
            float psum = 0.f;
            #pragma unroll
            for (int j = 0; j < 4; j++) {
                float p = __expf(s4[i][j] - mnew);
                s4[i][j] = p; psum += p;
            }
            #pragma unroll
            for (int off = 8; off; off >>= 1)
                psum += __shfl_xor_sync(0xffffffffu, psum, off);
            if (tx == 0) { mrow[row] = mnew; lrow[row] = lrow[row]*al + psum; }
            #pragma unroll
            for (int j = 0; j < 4; j++) acc[i][j] *= al;
        }

        __syncthreads();  // K reads done -> reuse KP for P
        #pragma unroll
        for (int i = 0; i < 4; i++)
            #pragma unroll
            for (int j = 0; j < 4; j++)
                KP[(tx*4 + j)*65 + ty*4 + i] = s4[i][j];   // Ps[k][q]
        __syncthreads();

        // O[q][d] += P[q][k] * V[k][d]
        #pragma unroll 8
        for (int k = 0; k < 64; k++) {
            float4 bv = *(const float4*)&Vs[k*64 + tx*4];
            float a0 = KP[k*65 + ty*4 + 0];
            float a1 = KP[k*65 + ty*4 + 1];
            float a2 = KP[k*65 + ty*4 + 2];
            float a3 = KP[k*65 + ty*4 + 3];
            acc[0][0] += a0*bv.x; acc[0][1] += a0*bv.y; acc[0][2] += a0*bv.z; acc[0][3] += a0*bv.w;
            acc[1][0] += a1*bv.x; acc[1][1] += a1*bv.y; acc[1][2] += a1*bv.z; acc[1][3] += a1*bv.w;
            acc[2][0] += a2*bv.x; acc[2][1] += a2*bv.y; acc[2][2] += a2*bv.z; acc[2][3] += a2*bv.w;
            acc[3][0] += a3*bv.x; acc[3][1] += a3*bv.y; acc[3][2] += a3*bv.z; acc[3][3] += a3*bv.w;
        }
    }

    #pragma unroll
    for (int i = 0; i < 4; i++) {
        float li = 1.0f / lrow[ty*4 + i];
        size_t base = ((size_t)(b*CN + q0 + ty*4 + i)) * CD + h*64 + tx*4;
        o[base + 0] = acc[i][0] * li;
        o[base + 1] = acc[i][1] * li;
        o[base + 2] = acc[i][2] * li;
        o[base + 3] = acc[i][3] * li;
    }
}

// ---------------- launch ----------------
extern "C" void kernel_launch(void* const* d_in, const int* in_sizes, int n_in,
                              void* d_out, int out_size)
{
    const float* x      = (const float*)d_in[0];
    const int*   ids    = (const int*)  d_in[1];
    const float* n1w    = (const float*)d_in[2];
    const float* n1b    = (const float*)d_in[3];
    const float* pin_w  = (const float*)d_in[4];
    const float* pout_w = (const float*)d_in[5];
    const float* pout_b = (const float*)d_in[6];
    const float* n2w    = (const float*)d_in[7];
    const float* n2b    = (const float*)d_in[8];
    const float* l1w    = (const float*)d_in[9];
    const float* l1b    = (const float*)d_in[10];
    const float* l2w    = (const float*)d_in[11];
    const float* l2b    = (const float*)d_in[12];
    float* out = (float*)d_out;

    float *xn, *qkv, *ao, *x1, *x2, *hh;
    cudaGetSymbolAddress((void**)&xn,  g_xn);
    cudaGetSymbolAddress((void**)&qkv, g_qkv);
    cudaGetSymbolAddress((void**)&ao,  g_ao);
    cudaGetSymbolAddress((void**)&x1,  g_x1);
    cudaGetSymbolAddress((void**)&x2,  g_x2);
    cudaGetSymbolAddress((void**)&hh,  g_h);

    cudaFuncSetAttribute(flash_k, cudaFuncAttributeMaxDynamicSharedMemorySize, 50176);

    // 1) xn = LN1(x)
    layernorm_k<<<NTOK, 256>>>(x, n1w, n1b, xn);
    // 2) qkv = xn @ Win^T
    gemm_nt<0><<<dim3(3*CD/128, NTOK/128), 256>>>(xn, pin_w, nullptr, nullptr, qkv, NTOK, 3*CD, CD);
    // 3) flash attention -> ao (already in [b,n,h*dh] layout)
    flash_k<<<dim3(CN/64, CH, CB), 256, 50176>>>(qkv, ids, ao);
    // 4) x1 = ao @ Wout^T + bout + xn
    gemm_nt<1><<<dim3(CD/128, NTOK/128), 256>>>(ao, pout_w, pout_b, xn, x1, NTOK, CD, CD);
    // 5) x2 = LN2(x1)
    layernorm_k<<<NTOK, 256>>>(x1, n2w, n2b, x2);
    // 6) h = gelu(x2 @ W1^T + b1)
    gemm_nt<2><<<dim3(CFF/128, NTOK/128), 256>>>(x2, l1w, l1b, nullptr, hh, NTOK, CFF, CD);
    // 7) out = h @ W2^T + b2 + x2
    gemm_nt<1><<<dim3(CD/128, NTOK/128), 256>>>(hh, l2w, l2b, x2, out, NTOK, CD, CFF);
}

// round 3
// speedup vs baseline: 2.3616x; 2.3616x over previous
#include <cuda_runtime.h>
#include <math.h>
#include <stdint.h>

#define CD   1024
#define CH   16
#define CFF  4096
#define CB   8
#define CN   1024
#define NTOK (CB*CN)   // 8192

// ---------------- scratch (no allocations allowed) ----------------
__device__ float g_xn [NTOK*CD];      // layernorm1(x), tf32-rounded
__device__ float g_qkv[NTOK*3*CD];    // qkv projection
__device__ float g_ao [NTOK*CD];      // attention output, tf32-rounded
__device__ float g_x1 [NTOK*CD];      // attn + residual
__device__ float g_x2 [NTOK*CD];      // layernorm2(x1), tf32-rounded
__device__ float g_h  [NTOK*CFF];     // gelu(lin1), tf32-rounded
__device__ float g_wq [3*CD*CD];      // tf32-rounded weights
__device__ float g_wo [CD*CD];
__device__ float g_w1 [CFF*CD];
__device__ float g_w2 [CD*CFF];

// ---------------- helpers ----------------
__device__ __forceinline__ uint32_t smem_u32(const void* p) {
    uint32_t a;
    asm("{ .reg .u64 t; cvta.to.shared.u64 t, %1; cvt.u32.u64 %0, t; }" : "=r"(a) : "l"(p));
    return a;
}
__device__ __forceinline__ float to_tf32(float x) {
    uint32_t u;
    asm("cvt.rna.tf32.f32 %0, %1;" : "=r"(u) : "f"(x));
    return __uint_as_float(u);
}
__device__ __forceinline__ void mma_tf32(float* d, const uint32_t* a, const uint32_t* b) {
    asm volatile(
        "mma.sync.aligned.m16n8k8.row.col.f32.tf32.tf32.f32 "
        "{%0,%1,%2,%3},{%4,%5,%6,%7},{%8,%9},{%0,%1,%2,%3};"
        : "+f"(d[0]), "+f"(d[1]), "+f"(d[2]), "+f"(d[3])
        : "r"(a[0]), "r"(a[1]), "r"(a[2]), "r"(a[3]), "r"(b[0]), "r"(b[1]));
}

// ---------------- tf32 RN rounding copy (weights) ----------------
__global__ void round_tf32_k(const float4* __restrict__ src, float4* __restrict__ dst, int n4) {
    int i = blockIdx.x * blockDim.x + threadIdx.x;
    if (i < n4) {
        float4 v = src[i];
        v.x = to_tf32(v.x); v.y = to_tf32(v.y); v.z = to_tf32(v.z); v.w = to_tf32(v.w);
        dst[i] = v;
    }
}

// ---------------- LayerNorm (output rounded to tf32) ----------------
__global__ void __launch_bounds__(256) layernorm_k(
    const float* __restrict__ x, const float* __restrict__ w,
    const float* __restrict__ b, float* __restrict__ y)
{
    int row = blockIdx.x;
    int tid = threadIdx.x;
    const float4* xr = (const float4*)(x + (size_t)row * CD);
    float4 xv = xr[tid];
    float s  = xv.x + xv.y + xv.z + xv.w;
    float ss = xv.x*xv.x + xv.y*xv.y + xv.z*xv.z + xv.w*xv.w;
    #pragma unroll
    for (int o = 16; o; o >>= 1) {
        s  += __shfl_xor_sync(0xffffffffu, s,  o);
        ss += __shfl_xor_sync(0xffffffffu, ss, o);
    }
    __shared__ float sm1[8], sm2[8];
    if ((tid & 31) == 0) { sm1[tid >> 5] = s; sm2[tid >> 5] = ss; }
    __syncthreads();
    float ts = 0.f, tss = 0.f;
    #pragma unroll
    for (int i = 0; i < 8; i++) { ts += sm1[i]; tss += sm2[i]; }
    float mu   = ts * (1.0f / CD);
    float var  = tss * (1.0f / CD) - mu * mu;
    float rstd = rsqrtf(var + 1e-5f);
    float4 wv = ((const float4*)w)[tid];
    float4 bv = ((const float4*)b)[tid];
    float4 ov;
    ov.x = to_tf32((xv.x - mu) * rstd * wv.x + bv.x);
    ov.y = to_tf32((xv.y - mu) * rstd * wv.y + bv.y);
    ov.z = to_tf32((xv.z - mu) * rstd * wv.z + bv.z);
    ov.w = to_tf32((xv.w - mu) * rstd * wv.w + bv.w);
    ((float4*)(y + (size_t)row * CD))[tid] = ov;
}

// ---------------- tf32 mma.sync NT GEMM ----------------
// C[M,N] = A[M,K] * B[N,K]^T.  CTA tile 128x256, K-chunk 32, 3-stage cp.async.
// SMEM rows padded to 36 floats: frag LDS banks = (4g+c)%32 -> conflict-free.
// EPI 0: none   EPI 1: +bias[n]+res[m,n]   EPI 2: tf32(gelu(+bias[n]))
#define NST     3
#define ROWF    36
#define ROWB    144u
#define A_FLT   (128*ROWF)            // 4608 floats
#define ST_FLT  (A_FLT + 256*ROWF)    // 13824 floats
#define ST_BYTE (ST_FLT*4)            // 55296 bytes
#define GSMEM   (NST*ST_BYTE)         // 165888

template<int EPI>
__global__ void __launch_bounds__(256, 1) gemm_mma(
    const float* __restrict__ A, const float* __restrict__ B,
    const float* __restrict__ bias, const float* __restrict__ res,
    float* __restrict__ C, int M, int N, int K)
{
    extern __shared__ float sm[];
    const uint32_t smb = smem_u32(sm);
    const int tid  = threadIdx.x;
    const int wid  = tid >> 5;
    const int lane = tid & 31;
    const int g = lane >> 2, c = lane & 3;
    const int wy = wid & 1, wx = wid >> 1;      // warp tile 64x64: (wy*64, wx*64)
    const int m0 = blockIdx.y * 128;
    const int n0 = blockIdx.x * 256;
    const int nch = K >> 5;

    // per-thread cp.async source/dest (A: 4 x 16B, B: 8 x 16B per chunk)
    const float* asrc[4]; uint32_t adst[4];
    const float* bsrc[8]; uint32_t bdst[8];
    #pragma unroll
    for (int i = 0; i < 4; i++) {
        int idx = tid + i * 256, row = idx >> 3, j = idx & 7;
        asrc[i] = A + (size_t)(m0 + row) * K + j * 4;
        adst[i] = row * ROWB + j * 16u;
    }
    #pragma unroll
    for (int i = 0; i < 8; i++) {
        int idx = tid + i * 256, row = idx >> 3, j = idx & 7;
        bsrc[i] = B + (size_t)(n0 + row) * K + j * 4;
        bdst[i] = (uint32_t)A_FLT * 4u + row * ROWB + j * 16u;
    }

    // prologue: stages 0..NST-2
    #pragma unroll
    for (int p = 0; p < NST - 1; p++) {
        uint32_t sb = smb + p * ST_BYTE;
        #pragma unroll
        for (int i = 0; i < 4; i++)
            asm volatile("cp.async.cg.shared.global [%0], [%1], 16;"
                         :: "r"(sb + adst[i]), "l"(asrc[i] + p * 32));
        #pragma unroll
        for (int i = 0; i < 8; i++)
            asm volatile("cp.async.cg.shared.global [%0], [%1], 16;"
                         :: "r"(sb + bdst[i]), "l"(bsrc[i] + p * 32));
        asm volatile("cp.async.commit_group;");
    }

    float acc[4][8][4] = {};
    const int aoff0 = (wy * 64 + g) * ROWF + c;
    const int boff0 = A_FLT + (wx * 64 + g) * ROWF + c;

    for (int ch = 0; ch < nch; ch++) {
        asm volatile("cp.async.wait_group %0;" :: "n"(NST - 2));
        __syncthreads();

        // issue chunk ch+NST-1 (overlap with compute)
        int ch2 = ch + NST - 1;
        if (ch2 < nch) {
            uint32_t sb = smb + (ch2 % NST) * ST_BYTE;
            #pragma unroll
            for (int i = 0; i < 4; i++)
                asm volatile("cp.async.cg.shared.global [%0], [%1], 16;"
                             :: "r"(sb + adst[i]), "l"(asrc[i] + ch2 * 32));
            #pragma unroll
            for (int i = 0; i < 8; i++)
                asm volatile("cp.async.cg.shared.global [%0], [%1], 16;"
                             :: "r"(sb + bdst[i]), "l"(bsrc[i] + ch2 * 32));
        }
        asm volatile("cp.async.commit_group;");

        const float* st = sm + (ch % NST) * ST_FLT;
        #pragma unroll
        for (int ks = 0; ks < 4; ks++) {
            int kb = ks * 8;
            uint32_t af[4][4], bf[8][2];
            #pragma unroll
            for (int mf = 0; mf < 4; mf++) {
                int base = aoff0 + mf * (16 * ROWF) + kb;
                af[mf][0] = __float_as_uint(st[base]);
                af[mf][1] = __float_as_uint(st[base + 8 * ROWF]);
                af[mf][2] = __float_as_uint(st[base + 4]);
                af[mf][3] = __float_as_uint(st[base + 8 * ROWF + 4]);
            }
            #pragma unroll
            for (int nf = 0; nf < 8; nf++) {
                int base = boff0 + nf * (8 * ROWF) + kb;
                bf[nf][0] = __float_as_uint(st[base]);
                bf[nf][1] = __float_as_uint(st[base + 4]);
            }
            #pragma unroll
            for (int mf = 0; mf < 4; mf++)
                #pragma unroll
                for (int nf = 0; nf < 8; nf++)
                    mma_tf32(acc[mf][nf], af[mf], bf[nf]);
        }
    }

    // epilogue
    const int mbase = m0 + wy * 64;
    const int nbase = n0 + wx * 64;
    #pragma unroll
    for (int mf = 0; mf < 4; mf++) {
        int r0 = mbase + mf * 16 + g;
        #pragma unroll
        for (int nf = 0; nf < 8; nf++) {
            int col = nbase + nf * 8 + c * 2;
            float v0 = acc[mf][nf][0], v1 = acc[mf][nf][1];
            float v2 = acc[mf][nf][2], v3 = acc[mf][nf][3];
            if (EPI >= 1) {
                float b0 = bias[col], b1 = bias[col + 1];
                v0 += b0; v1 += b1; v2 += b0; v3 += b1;
            }
            if (EPI == 1) {
                float2 r01 = *(const float2*)(res + (size_t)r0 * N + col);
                float2 r23 = *(const float2*)(res + (size_t)(r0 + 8) * N + col);
                v0 += r01.x; v1 += r01.y; v2 += r23.x; v3 += r23.y;
            }
            if (EPI == 2) {
                v0 = to_tf32(v0 * normcdff(v0));
                v1 = to_tf32(v1 * normcdff(v1));
                v2 = to_tf32(v2 * normcdff(v2));
                v3 = to_tf32(v3 * normcdff(v3));
            }
            *(float2*)(C + (size_t)r0 * N + col)       = make_float2(v0, v1);
            *(float2*)(C + (size_t)(r0 + 8) * N + col) = make_float2(v2, v3);
        }
    }
}

// ---------------- Flash attention (fp32 SIMT, output tf32-rounded) ----
__global__ void __launch_bounds__(256) flash_k(
    const float* __restrict__ qkv, const int* __restrict__ ids,
    float* __restrict__ o)
{
    extern __shared__ float sm[];
    float* Qs    = sm;                 // [64][64], Qs[d*64+q], pre-scaled
    float* KP    = sm + 4096;          // [64][65], Ks_t then Ps
    float* Vs    = sm + 4096 + 4160;   // [64][64]
    float* mrow  = Vs + 4096;
    float* lrow  = mrow + 64;
    float* maskb = lrow + 64;

    const int tid = threadIdx.x;
    const int tx = tid & 15, ty = tid >> 4;
    const int qt = blockIdx.x, h = blockIdx.y, b = blockIdx.z;
    const int q0 = qt * 64;
    const size_t rstr = 3 * CD;
    const float scale = 0.125f;

    for (int s5 = tid; s5 < 1024; s5 += 256) {
        int r = s5 >> 4, c4 = (s5 & 15) << 2;
        const float* gp = qkv + ((size_t)(b*CN + q0 + r)) * rstr + h*64 + c4;
        float4 v = *(const float4*)gp;
        Qs[(c4+0)*64 + r] = v.x * scale;
        Qs[(c4+1)*64 + r] = v.y * scale;
        Qs[(c4+2)*64 + r] = v.z * scale;
        Qs[(c4+3)*64 + r] = v.w * scale;
    }
    if (tid < 64) { mrow[tid] = -1e30f; lrow[tid] = 0.f; }

    float acc[4][4] = {};

    for (int kt = 0; kt < 16; kt++) {
        int k0 = kt * 64;
        __syncthreads();
        for (int s5 = tid; s5 < 1024; s5 += 256) {
            int r = s5 >> 4, c4 = (s5 & 15) << 2;
            const float* gk = qkv + ((size_t)(b*CN + k0 + r)) * rstr + CD   + h*64 + c4;
            float4 v = *(const float4*)gk;
            KP[(c4+0)*65 + r] = v.x; KP[(c4+1)*65 + r] = v.y;
            KP[(c4+2)*65 + r] = v.z; KP[(c4+3)*65 + r] = v.w;
            const float* gv = qkv + ((size_t)(b*CN + k0 + r)) * rstr + 2*CD + h*64 + c4;
            *(float4*)&Vs[r*64 + c4] = *(const float4*)gv;
        }
        if (tid < 64) maskb[tid] = -1.25e8f * (float)ids[b*CN + k0 + tid];
        __syncthreads();

        float s4[4][4] = {};
        #pragma unroll 8
        for (int d = 0; d < 64; d++) {
            float4 a = *(const float4*)&Qs[d*64 + ty*4];
            float b0 = KP[d*65 + tx*4 + 0];
            float b1 = KP[d*65 + tx*4 + 1];
            float b2 = KP[d*65 + tx*4 + 2];
            float b3 = KP[d*65 + tx*4 + 3];
            s4[0][0] += a.x*b0; s4[0][1] += a.x*b1; s4[0][2] += a.x*b2; s4[0][3] += a.x*b3;
            s4[1][0] += a.y*b0; s4[1][1] += a.y*b1; s4[1][2] += a.y*b2; s4[1][3] += a.y*b3;
            s4[2][0] += a.z*b0; s4[2][1] += a.z*b1; s4[2][2] += a.z*b2; s4[2][3] += a.z*b3;
            s4[3][0] += a.w*b0; s4[3][1] += a.w*b1; s4[3][2] += a.w*b2; s4[3][3] += a.w*b3;
        }
        float mb0 = maskb[tx*4+0], mb1 = maskb[tx*4+1], mb2 = maskb[tx*4+2], mb3 = maskb[tx*4+3];
        #pragma unroll
        for (int i = 0; i < 4; i++) {
            s4[i][0] += mb0; s4[i][1] += mb1; s4[i][2] += mb2; s4[i][3] += mb3;
        }

        #pragma unroll
        for (int i = 0; i < 4; i++) {
            float tmax = fmaxf(fmaxf(s4[i][0], s4[i][1]), fmaxf(s4[i][2], s4[i][3]));
            #pragma unroll
            for (int off = 8; off; off >>= 1)
                tmax = fmaxf(tmax, __shfl_xor_sync(0xffffffffu, tmax, off));
            int row = ty*4 + i;
            float mold = mrow[row];
            float mnew = fmaxf(mold, tmax);
            float al   = __expf(mold - mnew);
            float psum = 0.f;
            #pragma unroll
            for (int j = 0; j < 4; j++) {
                float p = __expf(s4[i][j] - mnew);
                s4[i][j] = p; psum += p;
            }
            #pragma unroll
            for (int off = 8; off; off >>= 1)
                psum += __shfl_xor_sync(0xffffffffu, psum, off);
            if (tx == 0) { mrow[row] = mnew; lrow[row] = lrow[row]*al + psum; }
            #pragma unroll
            for (int j = 0; j < 4; j++) acc[i][j] *= al;
        }

        __syncthreads();
        #pragma unroll
        for (int i = 0; i < 4; i++)
            #pragma unroll
            for (int j = 0; j < 4; j++)
                KP[(tx*4 + j)*65 + ty*4 + i] = s4[i][j];
        __syncthreads();

        #pragma unroll 8
        for (int k = 0; k < 64; k++) {
            float4 bv = *(const float4*)&Vs[k*64 + tx*4];
            float a0 = KP[k*65 + ty*4 + 0];
            float a1 = KP[k*65 + ty*4 + 1];
            float a2 = KP[k*65 + ty*4 + 2];
            float a3 = KP[k*65 + ty*4 + 3];
            acc[0][0] += a0*bv.x; acc[0][1] += a0*bv.y; acc[0][2] += a0*bv.z; acc[0][3] += a0*bv.w;
            acc[1][0] += a1*bv.x; acc[1][1] += a1*bv.y; acc[1][2] += a1*bv.z; acc[1][3] += a1*bv.w;
            acc[2][0] += a2*bv.x; acc[2][1] += a2*bv.y; acc[2][2] += a2*bv.z; acc[2][3] += a2*bv.w;
            acc[3][0] += a3*bv.x; acc[3][1] += a3*bv.y; acc[3][2] += a3*bv.z; acc[3][3] += a3*bv.w;
        }
    }

    #pragma unroll
    for (int i = 0; i < 4; i++) {
        float li = 1.0f / lrow[ty*4 + i];
        size_t base = ((size_t)(b*CN + q0 + ty*4 + i)) * CD + h*64 + tx*4;
        o[base + 0] = to_tf32(acc[i][0] * li);
        o[base + 1] = to_tf32(acc[i][1] * li);
        o[base + 2] = to_tf32(acc[i][2] * li);
        o[base + 3] = to_tf32(acc[i][3] * li);
    }
}

// ---------------- launch ----------------
extern "C" void kernel_launch(void* const* d_in, const int* in_sizes, int n_in,
                              void* d_out, int out_size)
{
    const float* x      = (const float*)d_in[0];
    const int*   ids    = (const int*)  d_in[1];
    const float* n1w    = (const float*)d_in[2];
    const float* n1b    = (const float*)d_in[3];
    const float* pin_w  = (const float*)d_in[4];
    const float* pout_w = (const float*)d_in[5];
    const float* pout_b = (const float*)d_in[6];
    const float* n2w    = (const float*)d_in[7];
    const float* n2b    = (const float*)d_in[8];
    const float* l1w    = (const float*)d_in[9];
    const float* l1b    = (const float*)d_in[10];
    const float* l2w    = (const float*)d_in[11];
    const float* l2b    = (const float*)d_in[12];
    float* out = (float*)d_out;

    float *xn, *qkv, *ao, *x1, *x2, *hh, *wq, *wo, *w1, *w2;
    cudaGetSymbolAddress((void**)&xn,  g_xn);
    cudaGetSymbolAddress((void**)&qkv, g_qkv);
    cudaGetSymbolAddress((void**)&ao,  g_ao);
    cudaGetSymbolAddress((void**)&x1,  g_x1);
    cudaGetSymbolAddress((void**)&x2,  g_x2);
    cudaGetSymbolAddress((void**)&hh,  g_h);
    cudaGetSymbolAddress((void**)&wq,  g_wq);
    cudaGetSymbolAddress((void**)&wo,  g_wo);
    cudaGetSymbolAddress((void**)&w1,  g_w1);
    cudaGetSymbolAddress((void**)&w2,  g_w2);

    cudaFuncSetAttribute(flash_k,     cudaFuncAttributeMaxDynamicSharedMemorySize, 50176);
    cudaFuncSetAttribute(gemm_mma<0>, cudaFuncAttributeMaxDynamicSharedMemorySize, GSMEM);
    cudaFuncSetAttribute(gemm_mma<1>, cudaFuncAttributeMaxDynamicSharedMemorySize, GSMEM);
    cudaFuncSetAttribute(gemm_mma<2>, cudaFuncAttributeMaxDynamicSharedMemorySize, GSMEM);

    // 0) round weights to tf32 (RN) into scratch copies
    round_tf32_k<<<(3*CD*CD/4 + 255)/256, 256>>>((const float4*)pin_w,  (float4*)wq, 3*CD*CD/4);
    round_tf32_k<<<(CD*CD/4   + 255)/256, 256>>>((const float4*)pout_w, (float4*)wo, CD*CD/4);
    round_tf32_k<<<(CFF*CD/4  + 255)/256, 256>>>((const float4*)l1w,    (float4*)w1, CFF*CD/4);
    round_tf32_k<<<(CD*CFF/4  + 255)/256, 256>>>((const float4*)l2w,    (float4*)w2, CD*CFF/4);

    // 1) xn = tf32(LN1(x))
    layernorm_k<<<NTOK, 256>>>(x, n1w, n1b, xn);
    // 2) qkv = xn @ Wq^T
    gemm_mma<0><<<dim3(3*CD/256, NTOK/128), 256, GSMEM>>>(xn, wq, nullptr, nullptr, qkv, NTOK, 3*CD, CD);
    // 3) flash attention -> ao (tf32-rounded)
    flash_k<<<dim3(CN/64, CH, CB), 256, 50176>>>(qkv, ids, ao);
    // 4) x1 = ao @ Wo^T + bout + xn
    gemm_mma<1><<<dim3(CD/256, NTOK/128), 256, GSMEM>>>(ao, wo, pout_b, xn, x1, NTOK, CD, CD);
    // 5) x2 = tf32(LN2(x1))
    layernorm_k<<<NTOK, 256>>>(x1, n2w, n2b, x2);
    // 6) h = tf32(gelu(x2 @ W1^T + b1))
    gemm_mma<2><<<dim3(CFF/256, NTOK/128), 256, GSMEM>>>(x2, w1, l1b, nullptr, hh, NTOK, CFF, CD);
    // 7) out = h @ W2^T + b2 + x2
    gemm_mma<1><<<dim3(CD/256, NTOK/128), 256, GSMEM>>>(hh, w2, l2b, x2, out, NTOK, CD, CFF);
}

// round 4
// speedup vs baseline: 3.1293x; 1.3251x over previous
#include <cuda_runtime.h>
#include <math.h>
#include <stdint.h>

#define CD   1024
#define CH   16
#define CFF  4096
#define CB   8
#define CN   1024
#define NTOK (CB*CN)   // 8192

// ---------------- scratch (no allocations allowed) ----------------
__device__ float g_xn [NTOK*CD];      // layernorm1(x), tf32-rounded
__device__ float g_qkv[NTOK*3*CD];    // qkv projection
__device__ float g_ao [NTOK*CD];      // attention output, tf32-rounded
__device__ float g_x1 [NTOK*CD];      // attn + residual
__device__ float g_x2 [NTOK*CD];      // layernorm2(x1), tf32-rounded
__device__ float g_h  [NTOK*CFF];     // gelu(lin1), tf32-rounded
__device__ float g_wq [3*CD*CD];      // tf32-rounded weights
__device__ float g_wo [CD*CD];
__device__ float g_w1 [CFF*CD];
__device__ float g_w2 [CD*CFF];

// ---------------- helpers ----------------
__device__ __forceinline__ uint32_t smem_u32(const void* p) {
    uint32_t a;
    asm("{ .reg .u64 t; cvta.to.shared.u64 t, %1; cvt.u32.u64 %0, t; }" : "=r"(a) : "l"(p));
    return a;
}
__device__ __forceinline__ float to_tf32(float x) {
    uint32_t u;
    asm("cvt.rna.tf32.f32 %0, %1;" : "=r"(u) : "f"(x));
    return __uint_as_float(u);
}
__device__ __forceinline__ void mma_tf32(float* d, const uint32_t* a, const uint32_t* b) {
    asm volatile(
        "mma.sync.aligned.m16n8k8.row.col.f32.tf32.tf32.f32 "
        "{%0,%1,%2,%3},{%4,%5,%6,%7},{%8,%9},{%0,%1,%2,%3};"
        : "+f"(d[0]), "+f"(d[1]), "+f"(d[2]), "+f"(d[3])
        : "r"(a[0]), "r"(a[1]), "r"(a[2]), "r"(a[3]), "r"(b[0]), "r"(b[1]));
}

// ---------------- tf32 RN rounding copy (weights) ----------------
__global__ void round_tf32_k(const float4* __restrict__ src, float4* __restrict__ dst, int n4) {
    int i = blockIdx.x * blockDim.x + threadIdx.x;
    if (i < n4) {
        float4 v = src[i];
        v.x = to_tf32(v.x); v.y = to_tf32(v.y); v.z = to_tf32(v.z); v.w = to_tf32(v.w);
        dst[i] = v;
    }
}

// ---------------- LayerNorm (output rounded to tf32) ----------------
__global__ void __launch_bounds__(256) layernorm_k(
    const float* __restrict__ x, const float* __restrict__ w,
    const float* __restrict__ b, float* __restrict__ y)
{
    int row = blockIdx.x;
    int tid = threadIdx.x;
    const float4* xr = (const float4*)(x + (size_t)row * CD);
    float4 xv = xr[tid];
    float s  = xv.x + xv.y + xv.z + xv.w;
    float ss = xv.x*xv.x + xv.y*xv.y + xv.z*xv.z + xv.w*xv.w;
    #pragma unroll
    for (int o = 16; o; o >>= 1) {
        s  += __shfl_xor_sync(0xffffffffu, s,  o);
        ss += __shfl_xor_sync(0xffffffffu, ss, o);
    }
    __shared__ float sm1[8], sm2[8];
    if ((tid & 31) == 0) { sm1[tid >> 5] = s; sm2[tid >> 5] = ss; }
    __syncthreads();
    float ts = 0.f, tss = 0.f;
    #pragma unroll
    for (int i = 0; i < 8; i++) { ts += sm1[i]; tss += sm2[i]; }
    float mu   = ts * (1.0f / CD);
    float var  = tss * (1.0f / CD) - mu * mu;
    float rstd = rsqrtf(var + 1e-5f);
    float4 wv = ((const float4*)w)[tid];
    float4 bv = ((const float4*)b)[tid];
    float4 ov;
    ov.x = to_tf32((xv.x - mu) * rstd * wv.x + bv.x);
    ov.y = to_tf32((xv.y - mu) * rstd * wv.y + bv.y);
    ov.z = to_tf32((xv.z - mu) * rstd * wv.z + bv.z);
    ov.w = to_tf32((xv.w - mu) * rstd * wv.w + bv.w);
    ((float4*)(y + (size_t)row * CD))[tid] = ov;
}

// ---------------- tf32 mma.sync NT GEMM ----------------
// C[M,N] = A[M,K] * B[N,K]^T.  CTA tile 128x256, K-chunk 32, 4-stage cp.async.
#define NST     4
#define ROWF    36
#define ROWB    144u
#define A_FLT   (128*ROWF)
#define ST_FLT  (A_FLT + 256*ROWF)
#define ST_BYTE (ST_FLT*4)            // 55296 bytes
#define GSMEM   (NST*ST_BYTE)         // 221184

template<int EPI>
__global__ void __launch_bounds__(256, 1) gemm_mma(
    const float* __restrict__ A, const float* __restrict__ B,
    const float* __restrict__ bias, const float* __restrict__ res,
    float* __restrict__ C, int M, int N, int K)
{
    extern __shared__ float sm[];
    const uint32_t smb = smem_u32(sm);
    const int tid  = threadIdx.x;
    const int wid  = tid >> 5;
    const int lane = tid & 31;
    const int g = lane >> 2, c = lane & 3;
    const int wy = wid & 1, wx = wid >> 1;
    const int m0 = blockIdx.y * 128;
    const int n0 = blockIdx.x * 256;
    const int nch = K >> 5;

    const float* asrc[4]; uint32_t adst[4];
    const float* bsrc[8]; uint32_t bdst[8];
    #pragma unroll
    for (int i = 0; i < 4; i++) {
        int idx = tid + i * 256, row = idx >> 3, j = idx & 7;
        asrc[i] = A + (size_t)(m0 + row) * K + j * 4;
        adst[i] = row * ROWB + j * 16u;
    }
    #pragma unroll
    for (int i = 0; i < 8; i++) {
        int idx = tid + i * 256, row = idx >> 3, j = idx & 7;
        bsrc[i] = B + (size_t)(n0 + row) * K + j * 4;
        bdst[i] = (uint32_t)A_FLT * 4u + row * ROWB + j * 16u;
    }

    #pragma unroll
    for (int p = 0; p < NST - 1; p++) {
        uint32_t sb = smb + p * ST_BYTE;
        #pragma unroll
        for (int i = 0; i < 4; i++)
            asm volatile("cp.async.cg.shared.global [%0], [%1], 16;"
                         :: "r"(sb + adst[i]), "l"(asrc[i] + p * 32));
        #pragma unroll
        for (int i = 0; i < 8; i++)
            asm volatile("cp.async.cg.shared.global [%0], [%1], 16;"
                         :: "r"(sb + bdst[i]), "l"(bsrc[i] + p * 32));
        asm volatile("cp.async.commit_group;");
    }

    float acc[4][8][4] = {};
    const int aoff0 = (wy * 64 + g) * ROWF + c;
    const int boff0 = A_FLT + (wx * 64 + g) * ROWF + c;

    for (int ch = 0; ch < nch; ch++) {
        asm volatile("cp.async.wait_group %0;" :: "n"(NST - 2));
        __syncthreads();

        int ch2 = ch + NST - 1;
        if (ch2 < nch) {
            uint32_t sb = smb + (ch2 % NST) * ST_BYTE;
            #pragma unroll
            for (int i = 0; i < 4; i++)
                asm volatile("cp.async.cg.shared.global [%0], [%1], 16;"
                             :: "r"(sb + adst[i]), "l"(asrc[i] + ch2 * 32));
            #pragma unroll
            for (int i = 0; i < 8; i++)
                asm volatile("cp.async.cg.shared.global [%0], [%1], 16;"
                             :: "r"(sb + bdst[i]), "l"(bsrc[i] + ch2 * 32));
        }
        asm volatile("cp.async.commit_group;");

        const float* st = sm + (ch % NST) * ST_FLT;
        #pragma unroll
        for (int ks = 0; ks < 4; ks++) {
            int kb = ks * 8;
            uint32_t af[4][4], bf[8][2];
            #pragma unroll
            for (int mf = 0; mf < 4; mf++) {
                int base = aoff0 + mf * (16 * ROWF) + kb;
                af[mf][0] = __float_as_uint(st[base]);
                af[mf][1] = __float_as_uint(st[base + 8 * ROWF]);
                af[mf][2] = __float_as_uint(st[base + 4]);
                af[mf][3] = __float_as_uint(st[base + 8 * ROWF + 4]);
            }
            #pragma unroll
            for (int nf = 0; nf < 8; nf++) {
                int base = boff0 + nf * (8 * ROWF) + kb;
                bf[nf][0] = __float_as_uint(st[base]);
                bf[nf][1] = __float_as_uint(st[base + 4]);
            }
            #pragma unroll
            for (int mf = 0; mf < 4; mf++)
                #pragma unroll
                for (int nf = 0; nf < 8; nf++)
                    mma_tf32(acc[mf][nf], af[mf], bf[nf]);
        }
    }

    const int mbase = m0 + wy * 64;
    const int nbase = n0 + wx * 64;
    #pragma unroll
    for (int mf = 0; mf < 4; mf++) {
        int r0 = mbase + mf * 16 + g;
        #pragma unroll
        for (int nf = 0; nf < 8; nf++) {
            int col = nbase + nf * 8 + c * 2;
            float v0 = acc[mf][nf][0], v1 = acc[mf][nf][1];
            float v2 = acc[mf][nf][2], v3 = acc[mf][nf][3];
            if (EPI >= 1) {
                float b0 = bias[col], b1 = bias[col + 1];
                v0 += b0; v1 += b1; v2 += b0; v3 += b1;
            }
            if (EPI == 1) {
                float2 r01 = *(const float2*)(res + (size_t)r0 * N + col);
                float2 r23 = *(const float2*)(res + (size_t)(r0 + 8) * N + col);
                v0 += r01.x; v1 += r01.y; v2 += r23.x; v3 += r23.y;
            }
            if (EPI == 2) {
                v0 = to_tf32(v0 * normcdff(v0));
                v1 = to_tf32(v1 * normcdff(v1));
                v2 = to_tf32(v2 * normcdff(v2));
                v3 = to_tf32(v3 * normcdff(v3));
            }
            *(float2*)(C + (size_t)r0 * N + col)       = make_float2(v0, v1);
            *(float2*)(C + (size_t)(r0 + 8) * N + col) = make_float2(v2, v3);
        }
    }
}

// ---------------- Flash attention with tf32 mma.sync ----------------
// Block = (b, h, 64-q-tile), 128 threads = 4 warps, warp owns 16 q rows.
// Smem: Qs[64][68], Ks[64][68] (row-major token x d), Vs[64][72], Ps[4][16][68].
#define FQ_STR 68
#define FV_STR 72
#define FSM_QS 0
#define FSM_KS (64*FQ_STR)                 // 4352
#define FSM_VS (FSM_KS + 64*FQ_STR)        // 8704
#define FSM_PS (FSM_VS + 64*FV_STR)        // 13312
#define FSM_MK (FSM_PS + 4*16*FQ_STR)      // 17664
#define FSM_TOT ((FSM_MK + 64) * 4)        // 70912 bytes

__global__ void __launch_bounds__(128) flashm_k(
    const float* __restrict__ qkv, const int* __restrict__ ids,
    float* __restrict__ o)
{
    extern __shared__ float sm[];
    float* Qs = sm + FSM_QS;
    float* Ks = sm + FSM_KS;
    float* Vs = sm + FSM_VS;
    float* mk = sm + FSM_MK;

    const int tid = threadIdx.x;
    const int wid = tid >> 5, lane = tid & 31;
    const int g = lane >> 2, c = lane & 3;
    const int qt = blockIdx.x, h = blockIdx.y, b = blockIdx.z;
    const int q0 = qt * 64;
    const size_t rstr = 3 * CD;
    float* Pw = sm + FSM_PS + wid * 16 * FQ_STR;

    // load Q tile (scaled by dh^-0.5, tf32-rounded)
    for (int i = tid; i < 1024; i += 128) {
        int r = i >> 4, c4 = (i & 15) << 2;
        float4 v = *(const float4*)(qkv + (size_t)(b*CN + q0 + r) * rstr + h*64 + c4);
        float* q = &Qs[r*FQ_STR + c4];
        q[0] = to_tf32(v.x * 0.125f); q[1] = to_tf32(v.y * 0.125f);
        q[2] = to_tf32(v.z * 0.125f); q[3] = to_tf32(v.w * 0.125f);
    }

    float oa[8][4] = {};
    float m0 = -1e30f, m1 = -1e30f, l0 = 0.f, l1 = 0.f;
    const float* Qw = Qs + (wid * 16) * FQ_STR;

    for (int kt = 0; kt < 16; kt++) {
        int k0 = kt * 64;
        __syncthreads();
        for (int i = tid; i < 1024; i += 128) {
            int r = i >> 4, c4 = (i & 15) << 2;
            const float* gk = qkv + (size_t)(b*CN + k0 + r) * rstr + CD + h*64 + c4;
            float4 v = *(const float4*)gk;
            float* kp = &Ks[r*FQ_STR + c4];
            kp[0] = to_tf32(v.x); kp[1] = to_tf32(v.y); kp[2] = to_tf32(v.z); kp[3] = to_tf32(v.w);
            float4 w = *(const float4*)(gk + CD);
            float* vp = &Vs[r*FV_STR + c4];
            vp[0] = to_tf32(w.x); vp[1] = to_tf32(w.y); vp[2] = to_tf32(w.z); vp[3] = to_tf32(w.w);
        }
        if (tid < 64) mk[tid] = -1.25e8f * (float)ids[b*CN + k0 + tid];
        __syncthreads();

        // ---- S = Q @ K^T (n-index = key token) ----
        float sa[8][4] = {};
        #pragma unroll
        for (int ks = 0; ks < 8; ks++) {
            uint32_t a[4];
            a[0] = __float_as_uint(Qw[g*FQ_STR + ks*8 + c]);
            a[1] = __float_as_uint(Qw[(g+8)*FQ_STR + ks*8 + c]);
            a[2] = __float_as_uint(Qw[g*FQ_STR + ks*8 + c + 4]);
            a[3] = __float_as_uint(Qw[(g+8)*FQ_STR + ks*8 + c + 4]);
            #pragma unroll
            for (int nf = 0; nf < 8; nf++) {
                uint32_t bb[2];
                bb[0] = __float_as_uint(Ks[(nf*8+g)*FQ_STR + ks*8 + c]);
                bb[1] = __float_as_uint(Ks[(nf*8+g)*FQ_STR + ks*8 + c + 4]);
                mma_tf32(sa[nf], a, bb);
            }
        }

        // ---- mask + online softmax (rows g and g+8) ----
        float rmax0 = -1e30f, rmax1 = -1e30f;
        #pragma unroll
        for (int nf = 0; nf < 8; nf++) {
            float mv0 = mk[nf*8 + 2*c], mv1 = mk[nf*8 + 2*c + 1];
            sa[nf][0] += mv0; sa[nf][1] += mv1;
            sa[nf][2] += mv0; sa[nf][3] += mv1;
            rmax0 = fmaxf(rmax0, fmaxf(sa[nf][0], sa[nf][1]));
            rmax1 = fmaxf(rmax1, fmaxf(sa[nf][2], sa[nf][3]));
        }
        rmax0 = fmaxf(rmax0, __shfl_xor_sync(0xffffffffu, rmax0, 1));
        rmax0 = fmaxf(rmax0, __shfl_xor_sync(0xffffffffu, rmax0, 2));
        rmax1 = fmaxf(rmax1, __shfl_xor_sync(0xffffffffu, rmax1, 1));
        rmax1 = fmaxf(rmax1, __shfl_xor_sync(0xffffffffu, rmax1, 2));
        float mn0 = fmaxf(m0, rmax0), mn1 = fmaxf(m1, rmax1);
        float al0 = __expf(m0 - mn0), al1 = __expf(m1 - mn1);
        m0 = mn0; m1 = mn1;
        float ps0 = 0.f, ps1 = 0.f;
        #pragma unroll
        for (int nf = 0; nf < 8; nf++) {
            float p0 = __expf(sa[nf][0] - mn0);
            float p1 = __expf(sa[nf][1] - mn0);
            float p2 = __expf(sa[nf][2] - mn1);
            float p3 = __expf(sa[nf][3] - mn1);
            ps0 += p0 + p1; ps1 += p2 + p3;
            // write P (tf32) to per-warp smem tile
            *(float2*)&Pw[g*FQ_STR + nf*8 + 2*c]     = make_float2(to_tf32(p0), to_tf32(p1));
            *(float2*)&Pw[(g+8)*FQ_STR + nf*8 + 2*c] = make_float2(to_tf32(p2), to_tf32(p3));
        }
        ps0 += __shfl_xor_sync(0xffffffffu, ps0, 1);
        ps0 += __shfl_xor_sync(0xffffffffu, ps0, 2);
        ps1 += __shfl_xor_sync(0xffffffffu, ps1, 1);
        ps1 += __shfl_xor_sync(0xffffffffu, ps1, 2);
        l0 = l0 * al0 + ps0;
        l1 = l1 * al1 + ps1;
        #pragma unroll
        for (int nf = 0; nf < 8; nf++) {
            oa[nf][0] *= al0; oa[nf][1] *= al0;
            oa[nf][2] *= al1; oa[nf][3] *= al1;
        }
        __syncwarp();

        // ---- O += P @ V (k-index = key token, n-index = d) ----
        #pragma unroll
        for (int ks = 0; ks < 8; ks++) {
            uint32_t a[4];
            a[0] = __float_as_uint(Pw[g*FQ_STR + ks*8 + c]);
            a[1] = __float_as_uint(Pw[(g+8)*FQ_STR + ks*8 + c]);
            a[2] = __float_as_uint(Pw[g*FQ_STR + ks*8 + c + 4]);
            a[3] = __float_as_uint(Pw[(g+8)*FQ_STR + ks*8 + c + 4]);
            #pragma unroll
            for (int nf = 0; nf < 8; nf++) {
                uint32_t bb[2];
                bb[0] = __float_as_uint(Vs[(ks*8 + c)*FV_STR + nf*8 + g]);
                bb[1] = __float_as_uint(Vs[(ks*8 + c + 4)*FV_STR + nf*8 + g]);
                mma_tf32(oa[nf], a, bb);
            }
        }
        __syncwarp();
    }

    // ---- epilogue: O /= l, tf32-round, store ----
    float inv0 = 1.0f / l0, inv1 = 1.0f / l1;
    size_t r0 = (size_t)(b*CN + q0 + wid*16 + g) * CD + h*64;
    size_t r1 = (size_t)(b*CN + q0 + wid*16 + g + 8) * CD + h*64;
    #pragma unroll
    for (int nf = 0; nf < 8; nf++) {
        int col = nf*8 + 2*c;
        *(float2*)(o + r0 + col) = make_float2(to_tf32(oa[nf][0]*inv0), to_tf32(oa[nf][1]*inv0));
        *(float2*)(o + r1 + col) = make_float2(to_tf32(oa[nf][2]*inv1), to_tf32(oa[nf][3]*inv1));
    }
}

// ---------------- launch ----------------
extern "C" void kernel_launch(void* const* d_in, const int* in_sizes, int n_in,
                              void* d_out, int out_size)
{
    const float* x      = (const float*)d_in[0];
    const int*   ids    = (const int*)  d_in[1];
    const float* n1w    = (const float*)d_in[2];
    const float* n1b    = (const float*)d_in[3];
    const float* pin_w  = (const float*)d_in[4];
    const float* pout_w = (const float*)d_in[5];
    const float* pout_b = (const float*)d_in[6];
    const float* n2w    = (const float*)d_in[7];
    const float* n2b    = (const float*)d_in[8];
    const float* l1w    = (const float*)d_in[9];
    const float* l1b    = (const float*)d_in[10];
    const float* l2w    = (const float*)d_in[11];
    const float* l2b    = (const float*)d_in[12];
    float* out = (float*)d_out;

    float *xn, *qkv, *ao, *x1, *x2, *hh, *wq, *wo, *w1, *w2;
    cudaGetSymbolAddress((void**)&xn,  g_xn);
    cudaGetSymbolAddress((void**)&qkv, g_qkv);
    cudaGetSymbolAddress((void**)&ao,  g_ao);
    cudaGetSymbolAddress((void**)&x1,  g_x1);
    cudaGetSymbolAddress((void**)&x2,  g_x2);
    cudaGetSymbolAddress((void**)&hh,  g_h);
    cudaGetSymbolAddress((void**)&wq,  g_wq);
    cudaGetSymbolAddress((void**)&wo,  g_wo);
    cudaGetSymbolAddress((void**)&w1,  g_w1);
    cudaGetSymbolAddress((void**)&w2,  g_w2);

    cudaFuncSetAttribute(flashm_k,    cudaFuncAttributeMaxDynamicSharedMemorySize, FSM_TOT);
    cudaFuncSetAttribute(gemm_mma<0>, cudaFuncAttributeMaxDynamicSharedMemorySize, GSMEM);
    cudaFuncSetAttribute(gemm_mma<1>, cudaFuncAttributeMaxDynamicSharedMemorySize, GSMEM);
    cudaFuncSetAttribute(gemm_mma<2>, cudaFuncAttributeMaxDynamicSharedMemorySize, GSMEM);

    // 0) round weights to tf32 (RN)
    round_tf32_k<<<(3*CD*CD/4 + 255)/256, 256>>>((const float4*)pin_w,  (float4*)wq, 3*CD*CD/4);
    round_tf32_k<<<(CD*CD/4   + 255)/256, 256>>>((const float4*)pout_w, (float4*)wo, CD*CD/4);
    round_tf32_k<<<(CFF*CD/4  + 255)/256, 256>>>((const float4*)l1w,    (float4*)w1, CFF*CD/4);
    round_tf32_k<<<(CD*CFF/4  + 255)/256, 256>>>((const float4*)l2w,    (float4*)w2, CD*CFF/4);

    // 1) xn = tf32(LN1(x))
    layernorm_k<<<NTOK, 256>>>(x, n1w, n1b, xn);
    // 2) qkv = xn @ Wq^T
    gemm_mma<0><<<dim3(3*CD/256, NTOK/128), 256, GSMEM>>>(xn, wq, nullptr, nullptr, qkv, NTOK, 3*CD, CD);
    // 3) flash attention (tensor-core) -> ao
    flashm_k<<<dim3(CN/64, CH, CB), 128, FSM_TOT>>>(qkv, ids, ao);
    // 4) x1 = ao @ Wo^T + bout + xn
    gemm_mma<1><<<dim3(CD/256, NTOK/128), 256, GSMEM>>>(ao, wo, pout_b, xn, x1, NTOK, CD, CD);
    // 5) x2 = tf32(LN2(x1))
    layernorm_k<<<NTOK, 256>>>(x1, n2w, n2b, x2);
    // 6) h = tf32(gelu(x2 @ W1^T + b1))
    gemm_mma<2><<<dim3(CFF/256, NTOK/128), 256, GSMEM>>>(x2, w1, l1b, nullptr, hh, NTOK, CFF, CD);
    // 7) out = h @ W2^T + b2 + x2
    gemm_mma<1><<<dim3(CD/256, NTOK/128), 256, GSMEM>>>(hh, w2, l2b, x2, out, NTOK, CD, CFF);
}